// round 1
// baseline (speedup 1.0000x reference)
#include <cuda_runtime.h>
#include <cstdint>

// Problem constants
#define BATCH 4
#define NPIX  4096      // 64*64 after space-to-depth
#define CDIM  256       // c * s * s
#define CQ    32        // CDIM / 8
#define HW    64        // H=W after s2d
#define S2    2

// Scratch (allocation-free rule: __device__ globals)
__device__ float g_q[(size_t)BATCH * NPIX * CQ];
__device__ float g_k[(size_t)BATCH * NPIX * CQ];
__device__ float g_v[(size_t)BATCH * NPIX * CDIM];
__device__ float g_o[(size_t)BATCH * NPIX * CDIM];

// ---------------------------------------------------------------------------
// Kernel 1: fused space-to-depth + Q/K/V 1x1-conv projections.
// xp[b, CC, h2, w2] = x[b, ci, 2*h2+hi, 2*w2+wi],  CC = wi*128 + hi*64 + ci.
// Each block: one (b, h2, whalf) -> 32 pixels. xs[pixel][CC] staged in smem.
// ---------------------------------------------------------------------------
__global__ __launch_bounds__(256) void proj_kernel(
    const float* __restrict__ x,
    const float* __restrict__ wq, const float* __restrict__ bq,
    const float* __restrict__ wk, const float* __restrict__ bk,
    const float* __restrict__ wv, const float* __restrict__ bv)
{
    __shared__ float xs[32][260];   // 32 pixels x 256 channels (pad 260 -> f4-aligned)
    const int whalf = blockIdx.x;   // 0..1
    const int h2    = blockIdx.y;   // 0..63
    const int b     = blockIdx.z;   // 0..3
    const int t     = threadIdx.x;

    // Load 128 source rows (ci,hi) x 64 w-contiguous floats, scatter to xs.
    #pragma unroll
    for (int i = 0; i < 32; i++) {
        int idx = i * 256 + t;          // 0..8191
        int row = idx >> 6;             // 0..127 = hi*64 + ci
        int j   = idx & 63;             // w offset within half-row
        int ci  = row & 63;
        int hi  = row >> 6;
        float val = x[(((size_t)(b * 64 + ci) * 128) + (2 * h2 + hi)) * 128
                      + whalf * 64 + j];
        int p  = j >> 1;
        int wi = j & 1;
        int CC = wi * 128 + hi * 64 + ci;
        xs[p][CC] = val;
    }
    __syncthreads();

    const int lane = t & 31;
    const int wid  = t >> 5;
    const int n    = h2 * 64 + whalf * 32 + lane;   // pixel index
    const float4* x4 = (const float4*)(&xs[lane][0]);  // lane stride 260 floats (16B aligned)

    // Each warp computes 40 of the 320 outputs for all 32 pixels (lane=pixel).
    for (int o = wid * 40; o < wid * 40 + 40; o++) {
        const float* wrow;
        float bias;
        float* dst;
        if (o < 32)      { wrow = wq + o * 256;        bias = bq[o];
                           dst = g_q + ((size_t)(b * NPIX + n)) * CQ + o; }
        else if (o < 64) { wrow = wk + (o - 32) * 256; bias = bk[o - 32];
                           dst = g_k + ((size_t)(b * NPIX + n)) * CQ + (o - 32); }
        else             { wrow = wv + (o - 64) * 256; bias = bv[o - 64];
                           dst = g_v + ((size_t)(b * NPIX + n)) * CDIM + (o - 64); }
        const float4* w4 = (const float4*)wrow;   // broadcast across warp
        float acc = bias;
        #pragma unroll 8
        for (int c4 = 0; c4 < 64; c4++) {
            float4 w = w4[c4];
            float4 xv = x4[c4];
            acc += w.x * xv.x + w.y * xv.y + w.z * xv.z + w.w * xv.w;
        }
        *dst = acc;
    }
}

// ---------------------------------------------------------------------------
// Kernel 2: flash attention, fp32.  BM = BN = 64, d_qk = 32, d_v = 256.
// Block = 256 threads: thread t owns row r = t&63, column block cb = t>>6
// (64 cols). Q row in registers, acc[64] in registers.
// S stored transposed St[j][r] -> conflict-free P reads; V reads broadcast.
// ---------------------------------------------------------------------------
#define SM_KS   0                 // 64*32   = 2048 floats
#define SM_VS   2048              // 64*260  = 16640 floats (f4 rows of 65)
#define SM_ST   (2048 + 16640)    // 64*64   = 4096 floats
#define SM_M    (SM_ST + 4096)    // 64
#define SM_L    (SM_M + 64)       // 64
#define SM_F    (SM_L + 64)       // 64
#define SM_RED  (SM_F + 64)       // 256
#define SM_TOT  (SM_RED + 256)    // 23232 floats = 92928 bytes

__global__ __launch_bounds__(256, 2) void attn_kernel()
{
    extern __shared__ float sm[];
    float* Ks  = sm + SM_KS;
    float* Vs  = sm + SM_VS;
    float* St  = sm + SM_ST;
    float* m_s = sm + SM_M;
    float* l_s = sm + SM_L;
    float* fct = sm + SM_F;
    float* red = sm + SM_RED;

    const int b  = blockIdx.y;
    const int n0 = blockIdx.x * 64;
    const int t  = threadIdx.x;
    const int r  = t & 63;
    const int cb = t >> 6;

    // Q row -> registers (4 threads share a row; L1 broadcast)
    float qreg[32];
    {
        const float4* qsrc = (const float4*)(g_q + ((size_t)(b * NPIX + n0 + r)) * CQ);
        #pragma unroll
        for (int i = 0; i < 8; i++) {
            float4 v = qsrc[i];
            qreg[4 * i + 0] = v.x; qreg[4 * i + 1] = v.y;
            qreg[4 * i + 2] = v.z; qreg[4 * i + 3] = v.w;
        }
    }

    float acc[64];
    #pragma unroll
    for (int c = 0; c < 64; c++) acc[c] = 0.0f;

    if (t < 64) { m_s[t] = -1e30f; l_s[t] = 0.0f; }

    for (int m0 = 0; m0 < NPIX; m0 += 64) {
        __syncthreads();   // protects Ks/Vs/St reuse (and first-iter m/l init)

        // cooperative loads: K tile (512 f4), V tile (4096 f4, padded rows)
        {
            const float4* ksrc = (const float4*)(g_k + ((size_t)(b * NPIX + m0)) * CQ);
            float4* Ks4 = (float4*)Ks;
            Ks4[t]       = ksrc[t];
            Ks4[t + 256] = ksrc[t + 256];
            const float4* vsrc = (const float4*)(g_v + ((size_t)(b * NPIX + m0)) * CDIM);
            float4* Vs4 = (float4*)Vs;
            #pragma unroll
            for (int i = 0; i < 16; i++) {
                int g  = i * 256 + t;
                int j  = g >> 6;
                int c4 = g & 63;
                Vs4[j * 65 + c4] = vsrc[g];
            }
        }
        __syncthreads();

        // S = Q K^T  (store transposed), per-thread 16 j values
        float pmax = -1e30f;
        #pragma unroll
        for (int jj = 0; jj < 16; jj++) {
            int j = cb * 16 + jj;
            const float4* krow = (const float4*)(Ks + j * 32);  // broadcast
            float s = 0.0f;
            #pragma unroll
            for (int c4 = 0; c4 < 8; c4++) {
                float4 kv = krow[c4];
                s += kv.x * qreg[4 * c4 + 0] + kv.y * qreg[4 * c4 + 1]
                   + kv.z * qreg[4 * c4 + 2] + kv.w * qreg[4 * c4 + 3];
            }
            St[j * 64 + r] = s;
            pmax = fmaxf(pmax, s);
        }
        red[cb * 64 + r] = pmax;
        __syncthreads();

        if (t < 64) {
            float M = fmaxf(fmaxf(red[t], red[64 + t]),
                            fmaxf(red[128 + t], red[192 + t]));
            float Mnew = fmaxf(m_s[t], M);
            fct[t] = __expf(m_s[t] - Mnew);
            m_s[t] = Mnew;
        }
        __syncthreads();

        // P = exp(S - m), partial row sums, rescale acc
        const float mrow = m_s[r];
        float psum = 0.0f;
        #pragma unroll
        for (int jj = 0; jj < 16; jj++) {
            int j = cb * 16 + jj;
            float p = __expf(St[j * 64 + r] - mrow);
            St[j * 64 + r] = p;
            psum += p;
        }
        red[cb * 64 + r] = psum;
        const float f = fct[r];
        #pragma unroll
        for (int c = 0; c < 64; c++) acc[c] *= f;
        __syncthreads();

        if (t < 64)
            l_s[t] = l_s[t] * fct[t] + red[t] + red[64 + t] + red[128 + t] + red[192 + t];

        // acc += P @ V   (V broadcast LDS128, pure-FFMA bound)
        #pragma unroll 2
        for (int j = 0; j < 64; j++) {
            float p = St[j * 64 + r];
            const float4* vrow = (const float4*)(Vs + j * 260 + cb * 64);
            #pragma unroll
            for (int c4 = 0; c4 < 16; c4++) {
                float4 v4 = vrow[c4];
                acc[c4 * 4 + 0] += p * v4.x;
                acc[c4 * 4 + 1] += p * v4.y;
                acc[c4 * 4 + 2] += p * v4.z;
                acc[c4 * 4 + 3] += p * v4.w;
            }
        }
    }
    __syncthreads();

    // normalize, stage through Vs, write coalesced
    const float linv = 1.0f / l_s[r];
    {
        float4* Vs4 = (float4*)Vs;
        #pragma unroll
        for (int c4 = 0; c4 < 16; c4++) {
            float4 o4;
            o4.x = acc[c4 * 4 + 0] * linv;
            o4.y = acc[c4 * 4 + 1] * linv;
            o4.z = acc[c4 * 4 + 2] * linv;
            o4.w = acc[c4 * 4 + 3] * linv;
            Vs4[r * 65 + cb * 16 + c4] = o4;
        }
    }
    __syncthreads();
    {
        float4* odst = (float4*)(g_o + ((size_t)(b * NPIX + n0)) * CDIM);
        float4* Vs4 = (float4*)Vs;
        #pragma unroll
        for (int i = 0; i < 16; i++) {
            int g  = i * 256 + t;
            int j  = g >> 6;
            int c4 = g & 63;
            odst[g] = Vs4[j * 65 + c4];
        }
    }
}

// ---------------------------------------------------------------------------
// Kernel 3: epilogue = gamma * out + xp, then depth-to-space, fp32 out.
// Coalesced on x read and final write.
// ---------------------------------------------------------------------------
__global__ __launch_bounds__(256) void epi_kernel(
    const float* __restrict__ x, const float* __restrict__ gamma,
    float* __restrict__ out)
{
    int idx = blockIdx.x * 256 + threadIdx.x;     // over 4*64*128*128
    int w  = idx & 127;
    int h  = (idx >> 7) & 127;
    int ci = (idx >> 14) & 63;
    int b  = idx >> 20;
    int h2 = h >> 1, hi = h & 1;
    int w2 = w >> 1, wi = w & 1;
    int CC = wi * 128 + hi * 64 + ci;
    int n  = h2 * 64 + w2;
    float g = __ldg(gamma);
    out[idx] = g * g_o[((size_t)(b * NPIX + n)) * CDIM + CC] + x[idx];
}

// ---------------------------------------------------------------------------
extern "C" void kernel_launch(void* const* d_in, const int* in_sizes, int n_in,
                              void* d_out, int out_size)
{
    const float* x     = (const float*)d_in[0];
    const float* wq    = (const float*)d_in[1];
    const float* bq    = (const float*)d_in[2];
    const float* wk    = (const float*)d_in[3];
    const float* bk    = (const float*)d_in[4];
    const float* wv    = (const float*)d_in[5];
    const float* bv    = (const float*)d_in[6];
    const float* gamma = (const float*)d_in[7];
    float* out = (float*)d_out;

    (void)in_sizes; (void)n_in; (void)out_size;

    // opt-in to >48KB dynamic smem (idempotent; not a stream op, capture-safe)
    cudaFuncSetAttribute(attn_kernel,
                         cudaFuncAttributeMaxDynamicSharedMemorySize,
                         SM_TOT * (int)sizeof(float));

    dim3 pgrid(2, 64, BATCH);
    proj_kernel<<<pgrid, 256>>>(x, wq, bq, wk, bk, wv, bv);

    dim3 agrid(NPIX / 64, BATCH);
    attn_kernel<<<agrid, 256, SM_TOT * sizeof(float)>>>();

    epi_kernel<<<(BATCH * 64 * 128 * 128) / 256, 256>>>(x, gamma, out);
}